// round 8
// baseline (speedup 1.0000x reference)
#include <cuda_runtime.h>
#include <cuda_fp16.h>
#include <math_constants.h>

// ---------------- problem constants ----------------
#define BATCH   32
#define Q_LEN   32
#define HID     128
#define DOC_LEN 128
#define K_CAND  256
#define K_OUT   16
#define N_PIDS  20000
#define N_EMB   (N_PIDS * DOC_LEN)

#define DPITCH  132   // doc smem pitch (floats): conflict-free LDS.64/cp.async

typedef unsigned long long u64;
typedef unsigned int u32;

// ---------------- device scratch ----------------
__device__ int    g_upids[BATCH * K_CAND];
__device__ int    g_ucnt[BATCH];
__device__ float  g_scores[BATCH * K_CAND];
// q pre-split fp16 B fragments: [b][s=8][t=4][lane=32] -> uint2 (b0,b1), hi & lo
__device__ uint2  g_qfh[BATCH * 8 * 4 * 32];
__device__ uint2  g_qfl[BATCH * 8 * 4 * 32];

// ---------------- helpers ----------------
__device__ __forceinline__ void split_h2(float2 v, u32& hi, u32& lo) {
    __half2 h = __float22half2_rn(v);
    float2 hf = __half22float2(h);
    __half2 l = __float22half2_rn(make_float2(v.x - hf.x, v.y - hf.y));
    hi = *reinterpret_cast<u32*>(&h);
    lo = *reinterpret_cast<u32*>(&l);
}
__device__ __forceinline__ void cp16(void* smem_dst, const void* gsrc) {
    u32 s = (u32)__cvta_generic_to_shared(smem_dst);
    asm volatile("cp.async.cg.shared.global [%0], [%1], 16;\n" :: "r"(s), "l"(gsrc));
}
template <int N>
__device__ __forceinline__ void cp_wait() {
    asm volatile("cp.async.wait_group %0;\n" :: "n"(N));
}
__device__ __forceinline__ void mma16(float* c, const u32* a, const u32* b) {
    asm volatile(
        "mma.sync.aligned.m16n8k16.row.col.f32.f16.f16.f32 "
        "{%0,%1,%2,%3}, {%4,%5,%6,%7}, {%8,%9}, {%0,%1,%2,%3};"
        : "+f"(c[0]), "+f"(c[1]), "+f"(c[2]), "+f"(c[3])
        : "r"(a[0]), "r"(a[1]), "r"(a[2]), "r"(a[3]), "r"(b[0]), "r"(b[1]));
}
// monotone map: ascending u32 <=> ascending float (works for -inf)
__device__ __forceinline__ u32 fmap(float f) {
    u32 s = __float_as_uint(f);
    return (s & 0x80000000u) ? ~s : (s | 0x80000000u);
}

// ---------------- kernel 1: prep (dedup for bid<32, qprep for bid>=32) -----
__global__ void prep_kernel(const void* idx_raw, const float* __restrict__ qv) {
    const int role = blockIdx.x >> 5;
    const int b    = blockIdx.x & 31;
    const int t    = threadIdx.x;

    if (role == 1) {
        // ---- qprep: pack q into pre-split fp16 hi/lo B fragments ----
        const float* src = qv + (size_t)b * Q_LEN * HID;
        uint2* dh = g_qfh + (size_t)b * (8 * 4 * 32);
        uint2* dl = g_qfl + (size_t)b * (8 * 4 * 32);
        for (int idx = t; idx < 8 * 4 * 32; idx += 256) {
            int s  = idx >> 7;
            int tt = (idx >> 5) & 3;
            int l  = idx & 31;
            int n  = 8 * tt + (l >> 2);
            int k0 = 16 * s + 2 * (l & 3);
            u32 b0h, b0l, b1h, b1l;
            split_h2(make_float2(src[n * HID + k0],     src[n * HID + k0 + 1]), b0h, b0l);
            split_h2(make_float2(src[n * HID + k0 + 8], src[n * HID + k0 + 9]), b1h, b1l);
            dh[idx] = make_uint2(b0h, b1h);
            dl[idx] = make_uint2(b0l, b1l);
        }
        return;
    }

    // ---- dedup: sorted unique pids ----
    __shared__ int pids[K_CAND];
    __shared__ int wsum[8];
    __shared__ int s_ok;

    if (t == 0) s_ok = 1;
    __syncthreads();
    if (t < 128) {
        long long v = ((const long long*)idx_raw)[b * 128 + t];
        if (v < 0 || v >= (long long)N_EMB) atomicAnd(&s_ok, 0);
    }
    __syncthreads();
    const int is64 = s_ok;

    long long v;
    if (is64) v = ((const long long*)idx_raw)[b * K_CAND + t];
    else      v = (long long)(((const int*)idx_raw)[b * K_CAND + t]);
    pids[t] = (int)(v >> 7);   // emb2pid[i] == i / 128
    __syncthreads();

    for (int k = 2; k <= K_CAND; k <<= 1) {
        for (int j = k >> 1; j > 0; j >>= 1) {
            int ixj = t ^ j;
            if (ixj > t) {
                int a = pids[t], c = pids[ixj];
                bool up = ((t & k) == 0);
                if ((a > c) == up) { pids[t] = c; pids[ixj] = a; }
            }
            __syncthreads();
        }
    }

    int myv  = pids[t];
    int flag = (t == 0) || (myv != pids[t - 1]);
    unsigned mask = __ballot_sync(0xffffffffu, flag);
    int lane = t & 31, w = t >> 5;
    int pre  = __popc(mask & ((1u << lane) - 1));
    if (lane == 31) wsum[w] = pre + flag;
    __syncthreads();
    int base = 0;
    for (int i = 0; i < w; i++) base += wsum[i];
    int pos = base + pre;
    if (flag) g_upids[b * K_CAND + pos] = myv;
    if (t == K_CAND - 1) g_ucnt[b] = pos + flag;
}

// ---------------- kernel 2: 3xFP16 m16n8k16 scoring, K-chunk pipelined -----
// Grid (BATCH, K_CAND): bid = b + 32*slot. Per-batch sorted-unique pid lists
// put equal pids at nearly-equal slots, so duplicates across batches are
// co-scheduled (32 consecutive bids) and the repeat fetch hits L2.
__global__ void __launch_bounds__(128, 3)
score_kernel(const float* __restrict__ vectors) {
    extern __shared__ float ds[];            // [DOC_LEN][DPITCH]
    __shared__ float red[4 * 32];

    const int b    = blockIdx.x;             // swapped vs round 7
    const int slot = blockIdx.y;
    const int tid  = threadIdx.x;
    const int wid  = tid >> 5;
    const int lane = tid & 31;

    if (slot >= g_ucnt[b]) {
        if (tid == 0) g_scores[b * K_CAND + slot] = -CUDART_INF_F;
        return;
    }
    const int pid = g_upids[b * K_CAND + slot];

    // stage doc tile in 4 K-chunks (columns 32c..32c+32), one commit group each
    const float* doc = vectors + (size_t)pid * DOC_LEN * HID;
#pragma unroll
    for (int c = 0; c < 4; c++) {
#pragma unroll
        for (int r = 0; r < 8; r++) {
            int i  = r * 128 + tid;          // 1024 cp16 per chunk
            int d  = i >> 3;                 // 8 x 16B per row-chunk
            int h4 = i & 7;
            cp16(ds + d * DPITCH + 32 * c + h4 * 4, doc + d * HID + 32 * c + h4 * 4);
        }
        asm volatile("cp.async.commit_group;\n" ::);
    }

    const int arow = lane >> 2;          // 0..7
    const int acol = 2 * (lane & 3);     // 0,2,4,6
    const uint2* qfh = g_qfh + (size_t)b * (8 * 4 * 32) + lane;
    const uint2* qfl = g_qfl + (size_t)b * (8 * 4 * 32) + lane;

    float acc[2][4][4];
#pragma unroll
    for (int mt = 0; mt < 2; mt++)
#pragma unroll
        for (int t = 0; t < 4; t++)
#pragma unroll
            for (int r = 0; r < 4; r++) acc[mt][t][r] = 0.0f;

#pragma unroll
    for (int c = 0; c < 4; c++) {
        if (c == 0) cp_wait<3>();
        else if (c == 1) cp_wait<2>();
        else if (c == 2) cp_wait<1>();
        else cp_wait<0>();
        __syncthreads();

#pragma unroll
        for (int si = 0; si < 2; si++) {
            const int s = 2 * c + si;           // k16 step 0..7
            const float* kb = ds + 16 * s + acol;

            u32 ahi[2][4], alo[2][4];
#pragma unroll
            for (int mt = 0; mt < 2; mt++) {
                int m0 = wid * 32 + mt * 16 + arow;
                float2 f0 = *(const float2*)(kb + m0 * DPITCH);
                float2 f1 = *(const float2*)(kb + (m0 + 8) * DPITCH);
                float2 f2 = *(const float2*)(kb + 8 + m0 * DPITCH);
                float2 f3 = *(const float2*)(kb + 8 + (m0 + 8) * DPITCH);
                split_h2(f0, ahi[mt][0], alo[mt][0]);
                split_h2(f1, ahi[mt][1], alo[mt][1]);
                split_h2(f2, ahi[mt][2], alo[mt][2]);
                split_h2(f3, ahi[mt][3], alo[mt][3]);
            }
#pragma unroll
            for (int t = 0; t < 4; t++) {
                uint2 vh = __ldg(&qfh[(s * 4 + t) * 32]);
                uint2 vl = __ldg(&qfl[(s * 4 + t) * 32]);
                u32 bh[2] = { vh.x, vh.y };
                u32 bl[2] = { vl.x, vl.y };
#pragma unroll
                for (int mt = 0; mt < 2; mt++) {
                    mma16(acc[mt][t], ahi[mt], bh);   // hi*hi
                    mma16(acc[mt][t], ahi[mt], bl);   // hi*lo
                    mma16(acc[mt][t], alo[mt], bh);   // lo*hi
                }
            }
        }
    }

    // epilogue: per-q max over this warp's 32 docs
#pragma unroll
    for (int t = 0; t < 4; t++) {
        float mx0 = fmaxf(acc[0][t][0], acc[0][t][2]);
        mx0 = fmaxf(mx0, fmaxf(acc[1][t][0], acc[1][t][2]));
        float mx1 = fmaxf(acc[0][t][1], acc[0][t][3]);
        mx1 = fmaxf(mx1, fmaxf(acc[1][t][1], acc[1][t][3]));
#pragma unroll
        for (int o = 4; o <= 16; o <<= 1) {
            mx0 = fmaxf(mx0, __shfl_xor_sync(0xffffffffu, mx0, o));
            mx1 = fmaxf(mx1, __shfl_xor_sync(0xffffffffu, mx1, o));
        }
        if (lane < 4) {
            red[wid * 32 + 8 * t + 2 * lane + 0] = mx0;
            red[wid * 32 + 8 * t + 2 * lane + 1] = mx1;
        }
    }
    __syncthreads();

    if (wid == 0) {
        float m = fmaxf(fmaxf(red[lane], red[32 + lane]),
                        fmaxf(red[64 + lane], red[96 + lane]));
#pragma unroll
        for (int o = 16; o > 0; o >>= 1)
            m += __shfl_xor_sync(0xffffffffu, m, o);
        if (lane == 0)
            g_scores[b * K_CAND + slot] = m * (1.0f / (float)Q_LEN);
    }
}

// ---------------- kernel 3: bitonic-sort top-16 ----------------------------
__global__ void topk_kernel(float* __restrict__ out, int out_size) {
    const int b = blockIdx.x;
    const int t = threadIdx.x;    // 256
    __shared__ u64 keys[K_CAND];

    float sc = g_scores[b * K_CAND + t];
    keys[t] = ((u64)(~fmap(sc)) << 32) | (u32)t;
    __syncthreads();

    for (int k = 2; k <= K_CAND; k <<= 1) {
        for (int j = k >> 1; j > 0; j >>= 1) {
            int ixj = t ^ j;
            if (ixj > t) {
                u64 a = keys[t], c = keys[ixj];
                bool up = ((t & k) == 0);
                if ((a > c) == up) { keys[t] = c; keys[ixj] = a; }
            }
            __syncthreads();
        }
    }

    if (t < K_OUT) {
        int slotw = (int)(keys[t] & 0xffffffffu);
        out[b * K_OUT + t] = (float)g_upids[b * K_CAND + slotw];
        if (out_size >= BATCH * K_OUT * 2)
            out[BATCH * K_OUT + b * K_OUT + t] = g_scores[b * K_CAND + slotw];
    }
}

// ---------------- launcher ----------------
extern "C" void kernel_launch(void* const* d_in, const int* in_sizes, int n_in,
                              void* d_out, int out_size) {
    int qi = 0, ii = 1, vi = 3;
    for (int i = 0; i < n_in; i++) {
        if (in_sizes[i] == BATCH * Q_LEN * HID)            qi = i;
        else if (in_sizes[i] == BATCH * K_CAND)            ii = i;
        else if (in_sizes[i] == N_PIDS * DOC_LEN * HID)    vi = i;
    }
    const float* q       = (const float*)d_in[qi];
    const void*  idx     = d_in[ii];
    const float* vectors = (const float*)d_in[vi];

    prep_kernel<<<64, 256>>>(idx, q);

    size_t smem = (size_t)(DOC_LEN * DPITCH) * sizeof(float);   // 67,584 B
    cudaFuncSetAttribute(score_kernel,
                         cudaFuncAttributeMaxDynamicSharedMemorySize, (int)smem);
    dim3 grid(BATCH, K_CAND);     // b fast, slot slow: dup pids co-scheduled
    score_kernel<<<grid, 128, smem>>>(vectors);

    topk_kernel<<<BATCH, K_CAND>>>((float*)d_out, out_size);
}

// round 9
// speedup vs baseline: 1.0179x; 1.0179x over previous
#include <cuda_runtime.h>
#include <cuda_fp16.h>
#include <math_constants.h>

// ---------------- problem constants ----------------
#define BATCH   32
#define Q_LEN   32
#define HID     128
#define DOC_LEN 128
#define K_CAND  256
#define K_OUT   16
#define N_PIDS  20000
#define N_EMB   (N_PIDS * DOC_LEN)

// fp16 chunk tile pitch: 40 halves (80 B) -> 20-bank row stride: 8 consecutive
// rows cover all 32 banks => conflict-free ldmatrix AND STS.64.
#define HPITCH_U32 20            // pitch in u32 (40 halves)

typedef unsigned long long u64;
typedef unsigned int u32;

// ---------------- device scratch ----------------
__device__ int    g_upids[BATCH * K_CAND];
__device__ int    g_ucnt[BATCH];
__device__ float  g_scores[BATCH * K_CAND];
// q pre-split fp16 B fragments: [b][s=8][t=4][lane=32] -> uint2 (b0,b1), hi & lo
__device__ uint2  g_qfh[BATCH * 8 * 4 * 32];
__device__ uint2  g_qfl[BATCH * 8 * 4 * 32];

// ---------------- helpers ----------------
__device__ __forceinline__ void split_h2(float2 v, u32& hi, u32& lo) {
    __half2 h = __float22half2_rn(v);
    float2 hf = __half22float2(h);
    __half2 l = __float22half2_rn(make_float2(v.x - hf.x, v.y - hf.y));
    hi = *reinterpret_cast<u32*>(&h);
    lo = *reinterpret_cast<u32*>(&l);
}
__device__ __forceinline__ void mma16(float* c, const u32* a, const u32* b) {
    asm volatile(
        "mma.sync.aligned.m16n8k16.row.col.f32.f16.f16.f32 "
        "{%0,%1,%2,%3}, {%4,%5,%6,%7}, {%8,%9}, {%0,%1,%2,%3};"
        : "+f"(c[0]), "+f"(c[1]), "+f"(c[2]), "+f"(c[3])
        : "r"(a[0]), "r"(a[1]), "r"(a[2]), "r"(a[3]), "r"(b[0]), "r"(b[1]));
}
__device__ __forceinline__ void ldmx4(u32* r, u32 addr) {
    asm volatile(
        "ldmatrix.sync.aligned.m8n8.x4.shared.b16 {%0,%1,%2,%3}, [%4];"
        : "=r"(r[0]), "=r"(r[1]), "=r"(r[2]), "=r"(r[3]) : "r"(addr));
}
// monotone map: ascending u32 <=> ascending float (works for -inf)
__device__ __forceinline__ u32 fmap(float f) {
    u32 s = __float_as_uint(f);
    return (s & 0x80000000u) ? ~s : (s | 0x80000000u);
}

// ---------------- kernel 1: prep (dedup for bid<32, qprep for bid>=32) -----
__global__ void prep_kernel(const void* idx_raw, const float* __restrict__ qv) {
    const int role = blockIdx.x >> 5;
    const int b    = blockIdx.x & 31;
    const int t    = threadIdx.x;

    if (role == 1) {
        const float* src = qv + (size_t)b * Q_LEN * HID;
        uint2* dh = g_qfh + (size_t)b * (8 * 4 * 32);
        uint2* dl = g_qfl + (size_t)b * (8 * 4 * 32);
        for (int idx = t; idx < 8 * 4 * 32; idx += 256) {
            int s  = idx >> 7;
            int tt = (idx >> 5) & 3;
            int l  = idx & 31;
            int n  = 8 * tt + (l >> 2);
            int k0 = 16 * s + 2 * (l & 3);
            u32 b0h, b0l, b1h, b1l;
            split_h2(make_float2(src[n * HID + k0],     src[n * HID + k0 + 1]), b0h, b0l);
            split_h2(make_float2(src[n * HID + k0 + 8], src[n * HID + k0 + 9]), b1h, b1l);
            dh[idx] = make_uint2(b0h, b1h);
            dl[idx] = make_uint2(b0l, b1l);
        }
        return;
    }

    // ---- dedup: sorted unique pids ----
    __shared__ int pids[K_CAND];
    __shared__ int wsum[8];
    __shared__ int s_ok;

    if (t == 0) s_ok = 1;
    __syncthreads();
    if (t < 128) {
        long long v = ((const long long*)idx_raw)[b * 128 + t];
        if (v < 0 || v >= (long long)N_EMB) atomicAnd(&s_ok, 0);
    }
    __syncthreads();
    const int is64 = s_ok;

    long long v;
    if (is64) v = ((const long long*)idx_raw)[b * K_CAND + t];
    else      v = (long long)(((const int*)idx_raw)[b * K_CAND + t]);
    pids[t] = (int)(v >> 7);   // emb2pid[i] == i / 128
    __syncthreads();

    for (int k = 2; k <= K_CAND; k <<= 1) {
        for (int j = k >> 1; j > 0; j >>= 1) {
            int ixj = t ^ j;
            if (ixj > t) {
                int a = pids[t], c = pids[ixj];
                bool up = ((t & k) == 0);
                if ((a > c) == up) { pids[t] = c; pids[ixj] = a; }
            }
            __syncthreads();
        }
    }

    int myv  = pids[t];
    int flag = (t == 0) || (myv != pids[t - 1]);
    unsigned mask = __ballot_sync(0xffffffffu, flag);
    int lane = t & 31, w = t >> 5;
    int pre  = __popc(mask & ((1u << lane) - 1));
    if (lane == 31) wsum[w] = pre + flag;
    __syncthreads();
    int base = 0;
    for (int i = 0; i < w; i++) base += wsum[i];
    int pos = base + pre;
    if (flag) g_upids[b * K_CAND + pos] = myv;
    if (t == K_CAND - 1) g_ucnt[b] = pos + flag;
}

// ---------------- kernel 2: 3xFP16 m16n8k16 scoring ------------------------
// Staging converts fp32 -> fp16 hi/lo smem tiles (out of the MMA chain);
// mainloop is ldmatrix + dense HMMA only. Double-buffered chunks (K=32 each).
__global__ void __launch_bounds__(128, 3)
score_kernel(const float* __restrict__ vectors) {
    __shared__ u32 sHI[2][DOC_LEN * HPITCH_U32];   // 10 KB x2
    __shared__ u32 sLO[2][DOC_LEN * HPITCH_U32];   // 10 KB x2
    __shared__ float red[4 * 32];

    const int b    = blockIdx.x;
    const int slot = blockIdx.y;
    const int tid  = threadIdx.x;
    const int wid  = tid >> 5;
    const int lane = tid & 31;

    if (slot >= g_ucnt[b]) {
        if (tid == 0) g_scores[b * K_CAND + slot] = -CUDART_INF_F;
        return;
    }
    const int pid = g_upids[b * K_CAND + slot];
    const float* doc = vectors + (size_t)pid * DOC_LEN * HID;

    // per-thread staging pattern: 8 rows {16r + tid>>3}, fixed col4 = 4*(tid&7)
    const int srow0 = tid >> 3;
    const int scol4 = 4 * (tid & 7);

    float4 bufA[8], bufB[8];
#pragma unroll
    for (int r = 0; r < 8; r++)
        bufA[r] = __ldg((const float4*)(doc + (16 * r + srow0) * HID + 0 * 32 + scol4));
#pragma unroll
    for (int r = 0; r < 8; r++)
        bufB[r] = __ldg((const float4*)(doc + (16 * r + srow0) * HID + 1 * 32 + scol4));

    const uint2* qfh = g_qfh + (size_t)b * (8 * 4 * 32) + lane;
    const uint2* qfl = g_qfl + (size_t)b * (8 * 4 * 32) + lane;
    const u32 hibase0 = (u32)__cvta_generic_to_shared(&sHI[0][0]);
    const u32 hibase1 = (u32)__cvta_generic_to_shared(&sHI[1][0]);
    const u32 lobase0 = (u32)__cvta_generic_to_shared(&sLO[0][0]);
    const u32 lobase1 = (u32)__cvta_generic_to_shared(&sLO[1][0]);

    float acc[2][4][4];
#pragma unroll
    for (int mt = 0; mt < 2; mt++)
#pragma unroll
        for (int t = 0; t < 4; t++)
#pragma unroll
            for (int r = 0; r < 4; r++) acc[mt][t][r] = 0.0f;

    // ldmatrix per-lane address offset (bytes): row (lane&15), half-col (lane>>4)
    const u32 lm_row = (u32)(lane & 15) * (HPITCH_U32 * 4);
    const u32 lm_col = (u32)(lane >> 4) * 16;

#pragma unroll
    for (int c = 0; c < 4; c++) {
        const int bsel = c & 1;
        const u32 hib = bsel ? hibase1 : hibase0;
        const u32 lob = bsel ? lobase1 : lobase0;
        u32* Hd = sHI[bsel];
        u32* Ld = sLO[bsel];

        // convert the chunk staged for c (bufA if c even, bufB if odd)
#pragma unroll
        for (int r = 0; r < 8; r++) {
            float4 v = (c & 1) ? bufB[r] : bufA[r];
            u32 h0, l0, h1, l1;
            split_h2(make_float2(v.x, v.y), h0, l0);
            split_h2(make_float2(v.z, v.w), h1, l1);
            int u = (16 * r + srow0) * HPITCH_U32 + (scol4 >> 1);
            *(uint2*)(Hd + u) = make_uint2(h0, h1);
            *(uint2*)(Ld + u) = make_uint2(l0, l1);
        }
        // prefetch chunk c+2 into the register buffer just freed
        if (c < 2) {
#pragma unroll
            for (int r = 0; r < 8; r++) {
                float4 v = __ldg((const float4*)(doc + (16 * r + srow0) * HID
                                                 + (c + 2) * 32 + scol4));
                if (c & 1) bufB[r] = v; else bufA[r] = v;
            }
        }
        __syncthreads();

#pragma unroll
        for (int si = 0; si < 2; si++) {
            const int s = 2 * c + si;           // k16 step 0..7
            // preload q fragments for this step (off the MMA chain)
            uint2 qh[4], ql[4];
#pragma unroll
            for (int t = 0; t < 4; t++) {
                qh[t] = __ldg(&qfh[(s * 4 + t) * 32]);
                ql[t] = __ldg(&qfl[(s * 4 + t) * 32]);
            }
            u32 ahi[2][4], alo[2][4];
#pragma unroll
            for (int mt = 0; mt < 2; mt++) {
                u32 off = (u32)((32 * wid + 16 * mt) * (HPITCH_U32 * 4))
                        + lm_row + 32 * si + lm_col;
                ldmx4(ahi[mt], hib + off);
                ldmx4(alo[mt], lob + off);
            }
#pragma unroll
            for (int t = 0; t < 4; t++) {
                u32 bh[2] = { qh[t].x, qh[t].y };
                u32 bl[2] = { ql[t].x, ql[t].y };
#pragma unroll
                for (int mt = 0; mt < 2; mt++) {
                    mma16(acc[mt][t], ahi[mt], bh);   // hi*hi
                    mma16(acc[mt][t], ahi[mt], bl);   // hi*lo
                    mma16(acc[mt][t], alo[mt], bh);   // lo*hi
                }
            }
        }
        __syncthreads();
    }

    // epilogue: per-q max over this warp's 32 docs
#pragma unroll
    for (int t = 0; t < 4; t++) {
        float mx0 = fmaxf(acc[0][t][0], acc[0][t][2]);
        mx0 = fmaxf(mx0, fmaxf(acc[1][t][0], acc[1][t][2]));
        float mx1 = fmaxf(acc[0][t][1], acc[0][t][3]);
        mx1 = fmaxf(mx1, fmaxf(acc[1][t][1], acc[1][t][3]));
#pragma unroll
        for (int o = 4; o <= 16; o <<= 1) {
            mx0 = fmaxf(mx0, __shfl_xor_sync(0xffffffffu, mx0, o));
            mx1 = fmaxf(mx1, __shfl_xor_sync(0xffffffffu, mx1, o));
        }
        if (lane < 4) {
            red[wid * 32 + 8 * t + 2 * lane + 0] = mx0;
            red[wid * 32 + 8 * t + 2 * lane + 1] = mx1;
        }
    }
    __syncthreads();

    if (wid == 0) {
        float m = fmaxf(fmaxf(red[lane], red[32 + lane]),
                        fmaxf(red[64 + lane], red[96 + lane]));
#pragma unroll
        for (int o = 16; o > 0; o >>= 1)
            m += __shfl_xor_sync(0xffffffffu, m, o);
        if (lane == 0)
            g_scores[b * K_CAND + slot] = m * (1.0f / (float)Q_LEN);
    }
}

// ---------------- kernel 3: bitonic-sort top-16 ----------------------------
__global__ void topk_kernel(float* __restrict__ out, int out_size) {
    const int b = blockIdx.x;
    const int t = threadIdx.x;    // 256
    __shared__ u64 keys[K_CAND];

    float sc = g_scores[b * K_CAND + t];
    keys[t] = ((u64)(~fmap(sc)) << 32) | (u32)t;
    __syncthreads();

    for (int k = 2; k <= K_CAND; k <<= 1) {
        for (int j = k >> 1; j > 0; j >>= 1) {
            int ixj = t ^ j;
            if (ixj > t) {
                u64 a = keys[t], c = keys[ixj];
                bool up = ((t & k) == 0);
                if ((a > c) == up) { keys[t] = c; keys[ixj] = a; }
            }
            __syncthreads();
        }
    }

    if (t < K_OUT) {
        int slotw = (int)(keys[t] & 0xffffffffu);
        out[b * K_OUT + t] = (float)g_upids[b * K_CAND + slotw];
        if (out_size >= BATCH * K_OUT * 2)
            out[BATCH * K_OUT + b * K_OUT + t] = g_scores[b * K_CAND + slotw];
    }
}

// ---------------- launcher ----------------
extern "C" void kernel_launch(void* const* d_in, const int* in_sizes, int n_in,
                              void* d_out, int out_size) {
    int qi = 0, ii = 1, vi = 3;
    for (int i = 0; i < n_in; i++) {
        if (in_sizes[i] == BATCH * Q_LEN * HID)            qi = i;
        else if (in_sizes[i] == BATCH * K_CAND)            ii = i;
        else if (in_sizes[i] == N_PIDS * DOC_LEN * HID)    vi = i;
    }
    const float* q       = (const float*)d_in[qi];
    const void*  idx     = d_in[ii];
    const float* vectors = (const float*)d_in[vi];

    prep_kernel<<<64, 256>>>(idx, q);

    dim3 grid(BATCH, K_CAND);
    score_kernel<<<grid, 128>>>(vectors);

    topk_kernel<<<BATCH, K_CAND>>>((float*)d_out, out_size);
}